// round 1
// baseline (speedup 1.0000x reference)
#include <cuda_runtime.h>

#define NN 8192
#define T 64
#define NT (NN / T)   // 128 tile-blocks per dimension

// Scratch (no allocations allowed): deterministic per-slot partial sums + d vector.
__device__ float g_part[NT][NN];   // 4 MB
__device__ float g_d[NN];

// ---------------------------------------------------------------------------
// Pass 1: rowsum partials. One block per upper-triangular 64x64 tile pair.
// part[k][i] = contribution to rowsum[i] from column-block k; each slot
// written exactly once (deterministic, no atomics).
// ---------------------------------------------------------------------------
__global__ __launch_bounds__(256) void pass1_kernel(const float* __restrict__ adj) {
    int bi = blockIdx.y, bj = blockIdx.x;
    if (bj < bi) return;

    __shared__ float s1[T][T + 1];
    __shared__ float s2[T][T + 1];
    __shared__ float rpart[T][2];
    __shared__ float cpart[4][T];

    int tid = threadIdx.x;
    int c = tid & 63;     // column within tile
    int q = tid >> 6;     // row quarter (0..3)
    bool diag = (bi == bj);

    const float* p1 = adj + (size_t)(bi * T) * NN + (size_t)(bj * T);
    #pragma unroll
    for (int k = 0; k < 16; k++) {
        int r = q * 16 + k;
        s1[r][c] = p1[(size_t)r * NN + c];
    }
    if (!diag) {
        const float* p2 = adj + (size_t)(bj * T) * NN + (size_t)(bi * T);
        #pragma unroll
        for (int k = 0; k < 16; k++) {
            int r = q * 16 + k;
            s2[r][c] = p2[(size_t)r * NN + c];
        }
    }
    __syncthreads();

    float cacc = 0.0f;
    #pragma unroll
    for (int k = 0; k < 16; k++) {
        int r = q * 16 + k;
        float v = diag ? fmaxf(s1[r][c], s1[c][r])
                       : fmaxf(s1[r][c], s2[c][r]);
        cacc += v;
        // row-sum: reduce across the 64 threads (2 warps) owning row r
        float rs = v;
        rs += __shfl_xor_sync(0xffffffffu, rs, 16);
        rs += __shfl_xor_sync(0xffffffffu, rs, 8);
        rs += __shfl_xor_sync(0xffffffffu, rs, 4);
        rs += __shfl_xor_sync(0xffffffffu, rs, 2);
        rs += __shfl_xor_sync(0xffffffffu, rs, 1);
        if ((tid & 31) == 0) rpart[r][(tid >> 5) & 1] = rs;
    }
    cpart[q][c] = cacc;
    __syncthreads();

    if (tid < T) {
        // row-sums of m -> rows in block bi, column-block bj
        float rs = rpart[tid][0] + rpart[tid][1];
        g_part[bj][bi * T + tid] = rs;
        if (!diag) {
            // col-sums of m -> rows in block bj, column-block bi
            float cs = cpart[0][tid] + cpart[1][tid] + cpart[2][tid] + cpart[3][tid];
            g_part[bi][bj * T + tid] = cs;
        }
    }
}

// ---------------------------------------------------------------------------
// d[i] = (1 + sum_k part[k][i])^-1/2   (rowsum >= 1, never inf)
// ---------------------------------------------------------------------------
__global__ __launch_bounds__(256) void reduce_d_kernel() {
    int i = blockIdx.x * blockDim.x + threadIdx.x;
    float s = 1.0f;  // self-loop
    #pragma unroll
    for (int k = 0; k < NT; k++) s += g_part[k][i];
    g_d[i] = rsqrtf(s);
}

// ---------------------------------------------------------------------------
// Pass 2: out[i][j] = d[i]*d[j]*(max(adj[i][j], adj[j][i]) + (i==j))
// One block per upper-triangular tile pair; writes both output tiles coalesced.
// ---------------------------------------------------------------------------
__global__ __launch_bounds__(256) void pass2_kernel(const float* __restrict__ adj,
                                                    float* __restrict__ out) {
    int bi = blockIdx.y, bj = blockIdx.x;
    if (bj < bi) return;

    __shared__ float s1[T][T + 1];
    __shared__ float s2[T][T + 1];
    __shared__ float sdA[T];
    __shared__ float sdB[T];

    int tid = threadIdx.x;
    int c = tid & 63;
    int q = tid >> 6;
    bool diag = (bi == bj);

    const float* p1 = adj + (size_t)(bi * T) * NN + (size_t)(bj * T);
    #pragma unroll
    for (int k = 0; k < 16; k++) {
        int r = q * 16 + k;
        s1[r][c] = p1[(size_t)r * NN + c];
    }
    if (!diag) {
        const float* p2 = adj + (size_t)(bj * T) * NN + (size_t)(bi * T);
        #pragma unroll
        for (int k = 0; k < 16; k++) {
            int r = q * 16 + k;
            s2[r][c] = p2[(size_t)r * NN + c];
        }
    }
    if (tid < T) sdA[tid] = g_d[bi * T + tid];
    else if (tid < 2 * T) sdB[tid - T] = g_d[bj * T + (tid - T)];
    __syncthreads();

    if (diag) {
        float* po = out + (size_t)(bi * T) * NN + (size_t)(bj * T);
        float dc = sdA[c];
        #pragma unroll
        for (int k = 0; k < 16; k++) {
            int r = q * 16 + k;
            float v = fmaxf(s1[r][c], s1[c][r]) + ((r == c) ? 1.0f : 0.0f);
            po[(size_t)r * NN + c] = sdA[r] * dc * v;
        }
    } else {
        float* po1 = out + (size_t)(bi * T) * NN + (size_t)(bj * T);
        float* po2 = out + (size_t)(bj * T) * NN + (size_t)(bi * T);
        float dcB = sdB[c];
        float dcA = sdA[c];
        #pragma unroll
        for (int k = 0; k < 16; k++) {
            int r = q * 16 + k;
            float v1 = fmaxf(s1[r][c], s2[c][r]);
            po1[(size_t)r * NN + c] = sdA[r] * dcB * v1;
            float v2 = fmaxf(s2[r][c], s1[c][r]);
            po2[(size_t)r * NN + c] = sdB[r] * dcA * v2;
        }
    }
}

extern "C" void kernel_launch(void* const* d_in, const int* in_sizes, int n_in,
                              void* d_out, int out_size) {
    const float* adj = (const float*)d_in[0];
    float* out = (float*)d_out;
    (void)in_sizes; (void)n_in; (void)out_size;

    dim3 grid(NT, NT);
    pass1_kernel<<<grid, 256>>>(adj);
    reduce_d_kernel<<<NN / 256, 256>>>();
    pass2_kernel<<<grid, 256>>>(adj, out);
}

// round 2
// speedup vs baseline: 1.0454x; 1.0454x over previous
#include <cuda_runtime.h>
#include <math.h>

#define NN 8192
#define T 64
#define NT (NN / T)          // 128 tile-blocks per dimension
#define NPAIRS (NT * (NT + 1) / 2)   // 8256 upper-tri tile pairs

// Scratch (no allocations allowed): deterministic per-slot partial sums + d vector.
__device__ float g_part[NT][NN];   // 4 MB
__device__ float g_d[NN];

// Decode linear upper-triangular pair index t -> (bi, bj), bj >= bi.
// S(b) = b*NT - b*(b-1)/2 is the first index of row b.
__device__ __forceinline__ void tri_decode(int t, int& bi, int& bj) {
    float a = 2.0f * NT + 1.0f;
    int b = (int)(0.5f * (a - sqrtf(a * a - 8.0f * (float)t)));
    if (b < 0) b = 0;
    if (b > NT - 1) b = NT - 1;
    while (b > 0 && (b * NT - b * (b - 1) / 2) > t) b--;
    while (((b + 1) * NT - (b + 1) * b / 2) <= t) b++;
    bi = b;
    bj = b + (t - (b * NT - b * (b - 1) / 2));
}

// Load one 64x64 tile with float4 LDG into padded shared (stride T+1).
__device__ __forceinline__ void load_tile(const float* __restrict__ src,
                                          float dst[T][T + 1], int tid) {
    int lf = tid & 15;      // float4 column 0..15
    int lr = tid >> 4;      // base row 0..15
    const float4* p = (const float4*)src;
    #pragma unroll
    for (int k = 0; k < 4; k++) {
        int r = lr + 16 * k;
        float4 x = p[(size_t)r * (NN / 4) + lf];
        dst[r][4 * lf + 0] = x.x;
        dst[r][4 * lf + 1] = x.y;
        dst[r][4 * lf + 2] = x.z;
        dst[r][4 * lf + 3] = x.w;
    }
}

// ---------------------------------------------------------------------------
// Pass 1: rowsum partials, one block per upper-tri tile pair. No shuffles:
// both the row-axis and col-axis reductions are plain accumulation loops with
// conflict-free shared access (stride 65). Each g_part slot written once.
// ---------------------------------------------------------------------------
__global__ __launch_bounds__(256, 6) void pass1_kernel(const float* __restrict__ adj) {
    __shared__ float s1[T][T + 1];
    __shared__ float s2[T][T + 1];
    __shared__ float rpart[4][T];
    __shared__ float cpart[4][T];

    int bi, bj;
    tri_decode(blockIdx.x, bi, bj);
    int tid = threadIdx.x;
    bool diag = (bi == bj);

    load_tile(adj + (size_t)(bi * T) * NN + (size_t)(bj * T), s1, tid);
    if (!diag)
        load_tile(adj + (size_t)(bj * T) * NN + (size_t)(bi * T), s2, tid);
    __syncthreads();

    int c = tid & 63;   // owned lane index (row for loop A, col for loop B)
    int q = tid >> 6;   // quarter 0..3

    if (diag) {
        // m symmetric: rowsum == colsum, compute rowsum only.
        float racc = 0.0f;
        #pragma unroll
        for (int j = 0; j < 16; j++) {
            int cc = q * 16 + j;
            racc += fmaxf(s1[c][cc], s1[cc][c]);
        }
        rpart[q][c] = racc;
        __syncthreads();
        if (tid < T)
            g_part[bi][bi * T + tid] =
                rpart[0][tid] + rpart[1][tid] + rpart[2][tid] + rpart[3][tid];
    } else {
        // Loop A: rowsum of m (rows of block bi). Thread owns row r=c.
        float racc = 0.0f;
        #pragma unroll
        for (int j = 0; j < 16; j++) {
            int cc = q * 16 + j;
            racc += fmaxf(s1[c][cc], s2[cc][c]);
        }
        // Loop B: colsum of m (rows of block bj). Thread owns column c.
        float cacc = 0.0f;
        #pragma unroll
        for (int j = 0; j < 16; j++) {
            int rr = q * 16 + j;
            cacc += fmaxf(s1[rr][c], s2[c][rr]);
        }
        rpart[q][c] = racc;
        cpart[q][c] = cacc;
        __syncthreads();
        if (tid < T) {
            g_part[bj][bi * T + tid] =
                rpart[0][tid] + rpart[1][tid] + rpart[2][tid] + rpart[3][tid];
        } else if (tid < 2 * T) {
            int u = tid - T;
            g_part[bi][bj * T + u] =
                cpart[0][u] + cpart[1][u] + cpart[2][u] + cpart[3][u];
        }
    }
}

// ---------------------------------------------------------------------------
// d[i] = (1 + sum_k part[k][i])^-1/2   (rowsum >= 1, never inf)
// ---------------------------------------------------------------------------
__global__ __launch_bounds__(256) void reduce_d_kernel() {
    int i = blockIdx.x * blockDim.x + threadIdx.x;
    float s = 1.0f;  // self-loop
    #pragma unroll 8
    for (int k = 0; k < NT; k++) s += g_part[k][i];
    g_d[i] = rsqrtf(s);
}

// ---------------------------------------------------------------------------
// Pass 2: out[i][j] = d[i]*d[j]*(max(adj[i][j], adj[j][i]) + (i==j))
// One block per upper-tri tile pair; writes both output tiles coalesced.
// ---------------------------------------------------------------------------
__global__ __launch_bounds__(256, 6) void pass2_kernel(const float* __restrict__ adj,
                                                       float* __restrict__ out) {
    __shared__ float s1[T][T + 1];
    __shared__ float s2[T][T + 1];
    __shared__ float sdA[T];
    __shared__ float sdB[T];

    int bi, bj;
    tri_decode(blockIdx.x, bi, bj);
    int tid = threadIdx.x;
    bool diag = (bi == bj);

    load_tile(adj + (size_t)(bi * T) * NN + (size_t)(bj * T), s1, tid);
    if (!diag)
        load_tile(adj + (size_t)(bj * T) * NN + (size_t)(bi * T), s2, tid);
    if (tid < T) sdA[tid] = g_d[bi * T + tid];
    else if (tid < 2 * T) sdB[tid - T] = g_d[bj * T + (tid - T)];
    __syncthreads();

    int c = tid & 63;
    int q = tid >> 6;

    if (diag) {
        float* po = out + (size_t)(bi * T) * NN + (size_t)(bi * T);
        float dc = sdA[c];
        #pragma unroll
        for (int j = 0; j < 16; j++) {
            int r = q * 16 + j;
            float v = fmaxf(s1[r][c], s1[c][r]) + ((r == c) ? 1.0f : 0.0f);
            po[(size_t)r * NN + c] = sdA[r] * dc * v;
        }
    } else {
        float* po1 = out + (size_t)(bi * T) * NN + (size_t)(bj * T);
        float* po2 = out + (size_t)(bj * T) * NN + (size_t)(bi * T);
        float dcB = sdB[c];
        float dcA = sdA[c];
        #pragma unroll
        for (int j = 0; j < 16; j++) {
            int r = q * 16 + j;
            float v1 = fmaxf(s1[r][c], s2[c][r]);
            po1[(size_t)r * NN + c] = sdA[r] * dcB * v1;
            float v2 = fmaxf(s2[r][c], s1[c][r]);
            po2[(size_t)r * NN + c] = sdB[r] * dcA * v2;
        }
    }
}

extern "C" void kernel_launch(void* const* d_in, const int* in_sizes, int n_in,
                              void* d_out, int out_size) {
    const float* adj = (const float*)d_in[0];
    float* out = (float*)d_out;
    (void)in_sizes; (void)n_in; (void)out_size;

    pass1_kernel<<<NPAIRS, 256>>>(adj);
    reduce_d_kernel<<<NN / 256, 256>>>();
    pass2_kernel<<<NPAIRS, 256>>>(adj, out);
}